// round 15
// baseline (speedup 1.0000x reference)
#include <cuda_runtime.h>
#include <cooperative_groups.h>
#include <cstdint>

namespace cg = cooperative_groups;

#define T_STEPS 512
#define BATCH   256
#define IN0     128
#define HID     256
#define G3      768   // 3*HID

// ---------------- scratch (static device arrays; allocation-free) ------------
__device__ float g_gi[(size_t)T_STEPS * BATCH * G3];   // reused by both layers
__device__ float g_h1[(size_t)T_STEPS * BATCH * HID];  // layer-0 outputs (tf32)
__device__ float g_h2[BATCH * HID];                    // final hidden state
__device__ float g_xt[(size_t)T_STEPS * BATCH * IN0];  // x pre-rounded to tf32
__device__ float g_wt[G3 * HID];                       // W_ih* pre-rounded

// ======================= helpers ========================
__device__ __forceinline__ float f2tf32(float x) {
    float r;
    asm("cvt.rna.tf32.f32 %0, %1;" : "=f"(r) : "f"(x));
    return r;
}

__device__ __forceinline__ void mma_tf32(float* d, const float* a, const float* b) {
    asm volatile(
        "mma.sync.aligned.m16n8k8.row.col.f32.tf32.tf32.f32 "
        "{%0,%1,%2,%3}, {%4,%5,%6,%7}, {%8,%9}, {%0,%1,%2,%3};"
        : "+f"(d[0]), "+f"(d[1]), "+f"(d[2]), "+f"(d[3])
        : "r"(__float_as_uint(a[0])), "r"(__float_as_uint(a[1])),
          "r"(__float_as_uint(a[2])), "r"(__float_as_uint(a[3])),
          "r"(__float_as_uint(b[0])), "r"(__float_as_uint(b[1])));
}

__device__ __forceinline__ void cp_async16(uint32_t dst, const void* src) {
    asm volatile("cp.async.cg.shared.global [%0], [%1], 16;"
                 :: "r"(dst), "l"(src) : "memory");
}

__device__ __forceinline__ float tanh_fast(float x) {
    float r;
    asm("tanh.approx.f32 %0, %1;" : "=f"(r) : "f"(x));
    return r;
}

#define MBAR_INIT(addr, cnt) \
    asm volatile("mbarrier.init.shared.b64 [%0], %1;" \
                 :: "r"((uint32_t)(addr)), "r"((uint32_t)(cnt)) : "memory")

#define MBAR_ARRIVE_RANK(local_addr, rk)                                        \
    asm volatile("{\n\t.reg .b32 ra;\n\t"                                       \
        "mapa.shared::cluster.u32 ra, %0, %1;\n\t"                              \
        "mbarrier.arrive.release.cluster.shared::cluster.b64 _, [ra];\n\t}"     \
        :: "r"((uint32_t)(local_addr)), "r"((uint32_t)(rk)) : "memory")

#define MBAR_WAIT(addr, par) do {                                               \
    uint32_t _m = (uint32_t)(addr); uint32_t _p = (uint32_t)(par); uint32_t _d; \
    asm volatile("{\n\t.reg .pred p;\n\t"                                       \
        "mbarrier.try_wait.parity.acquire.cluster.shared::cta.b64 p, [%1], %2;\n\t" \
        "selp.b32 %0, 1, 0, p;\n\t}"                                            \
        : "=r"(_d) : "r"(_m), "r"(_p) : "memory");                              \
    if (!_d) {                                                                  \
        asm volatile("{\n\t.reg .pred P1;\n\t"                                  \
            "WL_%=:\n\t"                                                        \
            "mbarrier.try_wait.parity.acquire.cluster.shared::cta.b64 P1, [%0], %1, 0x989680;\n\t" \
            "@P1 bra.uni WD_%=;\n\t"                                            \
            "bra.uni WL_%=;\n\t"                                                \
            "WD_%=:\n\t}"                                                       \
            :: "r"(_m), "r"(_p) : "memory");                                    \
    }                                                                           \
} while (0)

// =============================================================================
// Elementwise tf32-RNA pre-rounding (vectorized)
// =============================================================================
__global__ __launch_bounds__(256) void cvt_tf32_kernel(
    const float* __restrict__ s, float* __restrict__ d, int n4)
{
    const int i = blockIdx.x * 256 + threadIdx.x;
    if (i < n4) {
        float4 v = ((const float4*)s)[i];
        v.x = f2tf32(v.x); v.y = f2tf32(v.y);
        v.z = f2tf32(v.z); v.w = f2tf32(v.w);
        ((float4*)d)[i] = v;
    }
}

// =============================================================================
// gi GEMM v3: BK=32, 2-stage cp.async double buffer, pitch 40.
//  C[M,N] = A[M,K] @ Bw[N,K]^T + bias[N]; A/Bw pre-rounded tf32.
//  Halved barrier count vs v2; LDS.64 fragment loads conflict-free
//  (gid*20 mod 16 = {0,4,8,12} per 16-lane phase).
// =============================================================================
#define GP    40
#define GSTG  2
#define GEMM_SMEM_BYTES (GSTG * 2 * 128 * GP * 4)   // 81,920

__global__ __launch_bounds__(256, 2) void gemm_tf32_pipe(
    const float* __restrict__ A, const float* __restrict__ Bw,
    const float* __restrict__ bias, float* __restrict__ C,
    int N, int K)
{
    extern __shared__ float gsm[];
    const uint32_t smb = (uint32_t)__cvta_generic_to_shared(gsm);

    const int t    = threadIdx.x;
    const int bx   = blockIdx.x;
    const int by   = blockIdx.y;
    const int lane = t & 31;
    const int w    = t >> 5;
    const int wm   = w & 3;
    const int wn   = w >> 2;
    const int gid  = lane >> 2;
    const int tig  = lane & 3;

    const float* Agm = A  + (size_t)(by * 128) * K;
    const float* Bgm = Bw + (size_t)(bx * 128) * K;

    // copy identity: row = t>>1, half = (t&1)*16; 4 chunks per array per stage
    const int cm   = t >> 1;
    const int half = (t & 1) * 16;
    const uint32_t a_dst0 = smb + (cm * GP + half) * 4;
    const uint32_t b_dst0 = a_dst0 + (uint32_t)(GSTG * 128 * GP) * 4;
    const float* a_src0 = Agm + (size_t)cm * K + half;
    const float* b_src0 = Bgm + (size_t)cm * K + half;

    const int nst = K >> 5;

#define G_ISSUE(s_) do {                                                      \
    const uint32_t so_ = (uint32_t)(((s_) & 1) * 128 * GP) * 4;               \
    const int ko_ = (s_) * 32;                                                \
    cp_async16(a_dst0 + so_,      a_src0 + ko_);                              \
    cp_async16(a_dst0 + so_ + 16, a_src0 + ko_ + 4);                          \
    cp_async16(a_dst0 + so_ + 32, a_src0 + ko_ + 8);                          \
    cp_async16(a_dst0 + so_ + 48, a_src0 + ko_ + 12);                         \
    cp_async16(b_dst0 + so_,      b_src0 + ko_);                              \
    cp_async16(b_dst0 + so_ + 16, b_src0 + ko_ + 4);                          \
    cp_async16(b_dst0 + so_ + 32, b_src0 + ko_ + 8);                          \
    cp_async16(b_dst0 + so_ + 48, b_src0 + ko_ + 12);                         \
    asm volatile("cp.async.commit_group;" ::: "memory");                      \
} while (0)

    G_ISSUE(0);

    float acc[2][8][4];
#pragma unroll
    for (int i = 0; i < 2; i++)
#pragma unroll
        for (int jx = 0; jx < 8; jx++)
#pragma unroll
            for (int q = 0; q < 4; q++) acc[i][jx][q] = 0.0f;

    const int n0 = wn * 64;

    for (int s = 0; s < nst; s++) {
        if (s + 1 < nst) G_ISSUE(s + 1);
        if (s + 1 < nst) { asm volatile("cp.async.wait_group 1;" ::: "memory"); }
        else             { asm volatile("cp.async.wait_group 0;" ::: "memory"); }
        __syncthreads();                       // stage s visible

        const float* Asb = gsm + (s & 1) * 128 * GP;
        const float* Bsb = Asb + GSTG * 128 * GP;

#pragma unroll
        for (int kk = 0; kk < 32; kk += 8) {
            const int kc = kk + 2 * tig;
            float a[2][4], b[8][2];
#pragma unroll
            for (int i = 0; i < 2; i++) {
                const int m0 = wm * 32 + i * 16;
                const float2 lo = *(const float2*)(Asb + (m0 + gid) * GP + kc);
                const float2 hi = *(const float2*)(Asb + (m0 + gid + 8) * GP + kc);
                a[i][0] = lo.x; a[i][1] = hi.x; a[i][2] = lo.y; a[i][3] = hi.y;
            }
#pragma unroll
            for (int jx = 0; jx < 8; jx++) {
                const float2 bv = *(const float2*)(Bsb + (n0 + jx * 8 + gid) * GP + kc);
                b[jx][0] = bv.x; b[jx][1] = bv.y;
            }
#pragma unroll
            for (int i = 0; i < 2; i++)
#pragma unroll
                for (int jx = 0; jx < 8; jx++)
                    mma_tf32(acc[i][jx], a[i], b[jx]);
        }
        __syncthreads();                       // all reads of stage s done
    }

#pragma unroll
    for (int i = 0; i < 2; i++) {
        const int m0 = by * 128 + wm * 32 + i * 16 + gid;
#pragma unroll
        for (int jx = 0; jx < 8; jx++) {
            const int n = bx * 128 + wn * 64 + jx * 8 + tig * 2;
            const float b0 = __ldg(bias + n);
            const float b1 = __ldg(bias + n + 1);
            float2 v0, v1;
            v0.x = acc[i][jx][0] + b0;  v0.y = acc[i][jx][1] + b1;
            v1.x = acc[i][jx][2] + b0;  v1.y = acc[i][jx][3] + b1;
            *(float2*)(C + (size_t)m0 * N + n)       = v0;
            *(float2*)(C + (size_t)(m0 + 8) * N + n) = v1;
        }
    }
#undef G_ISSUE
}

// =============================================================================
// HMMA persistent GRU recurrence, v8: warps partitioned by (gate, k-slice).
//  Warp (g, s): all 64 rank cols of gate g over k-slice s (64 k) =
//  4 independent m16n8 tiles sharing ONE h-frag load per k-chunk:
//  h LDS.64/thread/step 32 -> 8 (these loads sit on the critical path right
//  after the mbar wait). Partials -> red[4][192][9]; gates sum 4 slices.
//  W stays register-resident (128 frag regs, same as v7); regs ~168.
//  Protocol/geometry/numerics class identical to rounds 10-14.
// =============================================================================
#define HPITCH 264
#define OFF_HBUF(par) ((par) * (8 * HPITCH))            // 2 x 2112 = 4224
#define OFF_RED       (2 * 8 * HPITCH)                  // 4224; 4*192*9 = 6912
#define OFF_GIS(par)  (OFF_RED + 6912 + (par) * 1536)   // 2 x 1536
#define OFF_BHH       (OFF_RED + 6912 + 2 * 1536)       // 192
#define OFF_MBAR      (OFF_BHH + 192)                   // 14400 (x4 -> 8B ok)
#define REC_SMEM_BYTES ((OFF_MBAR + 4) * 4)             // 57,616 B

__global__ void __cluster_dims__(4, 1, 1) __launch_bounds__(384, 1)
gru_rec_mma(const float* __restrict__ Whh, const float* __restrict__ bhh_g,
            const float* __restrict__ gi, float* __restrict__ hout,
            int store_all)
{
    extern __shared__ float smf[];
    float* red = smf + OFF_RED;
    float* bhh = smf + OFF_BHH;
    const uint32_t mbar = (uint32_t)__cvta_generic_to_shared(smf + OFF_MBAR);

    cg::cluster_group cluster = cg::this_cluster();
    const int rank = cluster.block_rank();
    const int B0   = (blockIdx.x >> 2) * 8;

    const int t    = threadIdx.x;
    const int lane = t & 31;
    const int w    = t >> 5;              // 0..11
    const int gid  = lane >> 2;           // 0..7
    const int tig  = lane & 3;            // 0..3
    const int g    = w >> 2;              // gate 0..2
    const int ks   = w & 3;               // k-slice 0..3 (64 k each)

    // ---- W_hh fragments -> registers: warp (g,ks) holds 4 col-tiles x 8
    // chunks; frag index = c*8+ch. k permuted (slot tig -> 2tig, tig+4 -> +1).
    float wa0[32], wa1[32], wa2[32], wa3[32];
#pragma unroll
    for (int c = 0; c < 4; c++) {
        const int r0 = g * 256 + rank * 64 + c * 16 + gid;
        const float* p0 = Whh + (size_t)r0 * 256 + ks * 64;
        const float* p1 = p0 + 8 * 256;
#pragma unroll
        for (int ch = 0; ch < 8; ch++) {
            wa0[c * 8 + ch] = f2tf32(p0[ch * 8 + 2 * tig]);
            wa1[c * 8 + ch] = f2tf32(p1[ch * 8 + 2 * tig]);
            wa2[c * 8 + ch] = f2tf32(p0[ch * 8 + 2 * tig + 1]);
            wa3[c * 8 + ch] = f2tf32(p1[ch * 8 + 2 * tig + 1]);
        }
    }
    for (int i = t; i < 192; i += 384)
        bhh[i] = bhh_g[((i >> 6) << 8) + rank * 64 + (i & 63)];
    for (int i = t; i < 2 * 8 * HPITCH; i += 384) smf[i] = 0.0f;
    if (t == 0) MBAR_INIT(mbar, 4);
    __syncthreads();
    cluster.sync();
    if (t < 4) MBAR_ARRIVE_RANK(mbar, t);

    const int j     = t & 63;
    const int bb    = (t >> 6) & 3;
    const int kglob = rank * 64 + j;
    float hprev0 = 0.0f, hprev1 = 0.0f;

    const int cb   = t / 48;
    const int crem = t % 48;
    const int cg_  = crem >> 4;
    const int cq   = crem & 15;
    const uint32_t gis_dst0 = (uint32_t)__cvta_generic_to_shared(
        smf + OFF_GIS(0) + cb * 192 + cg_ * 64 + cq * 4);
    const float* gi_src0 = gi + ((size_t)B0 + cb) * G3 + cg_ * 256 + rank * 64 + cq * 4;

    cp_async16(gis_dst0, gi_src0);
    asm volatile("cp.async.commit_group;" ::: "memory");

    for (int ts = 0; ts < T_STEPS; ts++) {
        const int par = ts & 1;
        {
            const int tn = (ts + 1 < T_STEPS) ? (ts + 1) : ts;
            cp_async16(gis_dst0 + (par ^ 1) * 1536 * 4,
                       gi_src0 + (size_t)tn * BATCH * G3);
            asm volatile("cp.async.commit_group;" ::: "memory");
        }

        MBAR_WAIT(mbar, par);

        // ---- GEMM: 4 col-tiles of gate g over k-slice ks; 1 h-load/chunk ----
        {
            float acc[4][4];
#pragma unroll
            for (int c = 0; c < 4; c++)
#pragma unroll
                for (int q = 0; q < 4; q++) acc[c][q] = 0.0f;

            const float* hb = smf + OFF_HBUF(par) + gid * HPITCH + ks * 64 + 2 * tig;
#pragma unroll
            for (int ch = 0; ch < 8; ch++) {
                const float2 hv = *(const float2*)(hb + ch * 8);
                float b[2] = { hv.x, hv.y };
#pragma unroll
                for (int c = 0; c < 4; c++) {
                    float a[4] = { wa0[c * 8 + ch], wa1[c * 8 + ch],
                                   wa2[c * 8 + ch], wa3[c * 8 + ch] };
                    mma_tf32(acc[c], a, b);
                }
            }
            // partials -> red[ks][g*64 + col][batch], pitch 9
#pragma unroll
            for (int c = 0; c < 4; c++) {
                const int a0 = (ks * 192 + g * 64 + c * 16 + gid) * 9 + 2 * tig;
                red[a0]          = acc[c][0];
                red[a0 + 1]      = acc[c][1];
                red[a0 + 72]     = acc[c][2];   // +8 rows
                red[a0 + 72 + 1] = acc[c][3];
            }
        }
        asm volatile("cp.async.wait_group 1;" ::: "memory");
        __syncthreads();                               // red + gi_s[par] ready

        // ---- gates: 4-slice reduction + exact-register h update ----
        if (t < 256) {
            const float* gis = smf + OFF_GIS(par);
            float* hwr = smf + OFF_HBUF(par ^ 1);
            const float br = bhh[j], bz = bhh[64 + j], bn = bhh[128 + j];
#pragma unroll
            for (int i = 0; i < 2; i++) {
                const int b = bb + 4 * i;
                const int r0 = (j)       * 9 + b;
                const int z0 = (64 + j)  * 9 + b;
                const int n0 = (128 + j) * 9 + b;
                const float hr = ((red[r0] + red[1728 + r0]) +
                                  (red[3456 + r0] + red[5184 + r0])) + br;
                const float hz = ((red[z0] + red[1728 + z0]) +
                                  (red[3456 + z0] + red[5184 + z0])) + bz;
                const float hn = ((red[n0] + red[1728 + n0]) +
                                  (red[3456 + n0] + red[5184 + n0])) + bn;
                const float ir  = gis[b * 192 + j];
                const float iz  = gis[b * 192 + 64 + j];
                const float in_ = gis[b * 192 + 128 + j];
                const float r = __fdividef(1.0f, 1.0f + __expf(-(ir + hr)));
                const float z = __fdividef(1.0f, 1.0f + __expf(-(iz + hz)));
                const float n = tanh_fast(in_ + r * hn);
                const float hprev = (i == 0) ? hprev0 : hprev1;
                const float hnew  = (1.0f - z) * n + z * hprev;
                if (i == 0) hprev0 = hnew; else hprev1 = hnew;

                const float hop = f2tf32(hnew);
                float* lp = hwr + b * HPITCH + kglob;
#pragma unroll
                for (int q = 0; q < 4; q++)
                    *(float*)cluster.map_shared_rank(lp, q) = hop;

                if (store_all) {
                    hout[((size_t)ts * BATCH + B0 + b) * HID + kglob] = hop;
                } else if (ts == T_STEPS - 1) {
                    hout[(size_t)(B0 + b) * HID + kglob] = hnew;
                }
            }
        }
        __syncthreads();
        if (t < 4) MBAR_ARRIVE_RANK(mbar, t);
    }

    cluster.sync();
}

// =============================================================================
// FC on the last hidden state
// =============================================================================
__global__ __launch_bounds__(256) void fc_kernel(
    const float* __restrict__ Wfc, const float* __restrict__ bfc,
    float* __restrict__ out)
{
    __shared__ float hs[256];
    const int b = blockIdx.x;
    const int o = threadIdx.x;
    hs[o] = g_h2[b * 256 + o];
    __syncthreads();
    const float* wr = Wfc + (size_t)o * 256;
    float acc = 0.0f;
#pragma unroll 8
    for (int k = 0; k < 256; k += 4) {
        const float4 wv = *(const float4*)(wr + k);
        acc += hs[k] * wv.x + hs[k + 1] * wv.y + hs[k + 2] * wv.z + hs[k + 3] * wv.w;
    }
    out[b * 256 + o] = acc + bfc[o];
}

// =============================================================================
extern "C" void kernel_launch(void* const* d_in, const int* in_sizes, int n_in,
                              void* d_out, int out_size)
{
    const float* x     = (const float*)d_in[0];
    const float* W_ih0 = (const float*)d_in[1];
    const float* W_hh0 = (const float*)d_in[2];
    const float* b_ih0 = (const float*)d_in[3];
    const float* b_hh0 = (const float*)d_in[4];
    const float* W_ih1 = (const float*)d_in[5];
    const float* W_hh1 = (const float*)d_in[6];
    const float* b_ih1 = (const float*)d_in[7];
    const float* b_hh1 = (const float*)d_in[8];
    const float* W_fc  = (const float*)d_in[9];
    const float* b_fc  = (const float*)d_in[10];
    float* out = (float*)d_out;

    float *gi_p, *h1_p, *h2_p, *xt_p, *wt_p;
    cudaGetSymbolAddress((void**)&gi_p, g_gi);
    cudaGetSymbolAddress((void**)&h1_p, g_h1);
    cudaGetSymbolAddress((void**)&h2_p, g_h2);
    cudaGetSymbolAddress((void**)&xt_p, g_xt);
    cudaGetSymbolAddress((void**)&wt_p, g_wt);

    cudaFuncSetAttribute(gru_rec_mma, cudaFuncAttributeMaxDynamicSharedMemorySize,
                         REC_SMEM_BYTES);
    cudaFuncSetAttribute(gemm_tf32_pipe, cudaFuncAttributeMaxDynamicSharedMemorySize,
                         GEMM_SMEM_BYTES);

    const int M = T_STEPS * BATCH;        // 131072
    dim3 gemm_grid(G3 / 128, M / 128);    // (6, 1024)

    // pre-round x and W_ih0 to tf32 (RNA)
    {
        const int n4x = (M * IN0) / 4;
        cvt_tf32_kernel<<<(n4x + 255) / 256, 256>>>(x, xt_p, n4x);
        const int n4w = (G3 * IN0) / 4;
        cvt_tf32_kernel<<<(n4w + 255) / 256, 256>>>(W_ih0, wt_p, n4w);
    }
    // layer 0: gi0 = x @ W_ih0^T + b_ih0   (BK=32 pipelined tf32 HMMA)
    gemm_tf32_pipe<<<gemm_grid, 256, GEMM_SMEM_BYTES>>>(xt_p, wt_p, b_ih0, gi_p, G3, IN0);
    // layer 0 recurrence -> g_h1[T,B,H] (stored pre-rounded tf32)
    gru_rec_mma<<<128, 384, REC_SMEM_BYTES>>>(W_hh0, b_hh0, gi_p, h1_p, 1);
    // pre-round W_ih1
    {
        const int n4w = (G3 * HID) / 4;
        cvt_tf32_kernel<<<(n4w + 255) / 256, 256>>>(W_ih1, wt_p, n4w);
    }
    // layer 1: gi1 = h1 @ W_ih1^T + b_ih1  (BK=32 pipelined tf32 HMMA)
    gemm_tf32_pipe<<<gemm_grid, 256, GEMM_SMEM_BYTES>>>(h1_p, wt_p, b_ih1, gi_p, G3, HID);
    // layer 1 recurrence -> g_h2[B,H]
    gru_rec_mma<<<128, 384, REC_SMEM_BYTES>>>(W_hh1, b_hh1, gi_p, h2_p, 0);
    // FC head
    fc_kernel<<<BATCH, 256>>>(W_fc, b_fc, out);
}

// round 16
// speedup vs baseline: 1.0421x; 1.0421x over previous
#include <cuda_runtime.h>
#include <cooperative_groups.h>
#include <cstdint>

namespace cg = cooperative_groups;

#define T_STEPS 512
#define BATCH   256
#define IN0     128
#define HID     256
#define G3      768   // 3*HID

// ---------------- scratch (static device arrays; allocation-free) ------------
__device__ float g_gi[(size_t)T_STEPS * BATCH * G3];   // reused by both layers
__device__ float g_h1[(size_t)T_STEPS * BATCH * HID];  // layer-0 outputs (tf32)
__device__ float g_h2[BATCH * HID];                    // final hidden state
__device__ float g_xt[(size_t)T_STEPS * BATCH * IN0];  // x pre-rounded to tf32
__device__ float g_wt[G3 * HID];                       // W_ih* pre-rounded

// ======================= helpers ========================
__device__ __forceinline__ float f2tf32(float x) {
    float r;
    asm("cvt.rna.tf32.f32 %0, %1;" : "=f"(r) : "f"(x));
    return r;
}

__device__ __forceinline__ void mma_tf32(float* d, const float* a, const float* b) {
    asm volatile(
        "mma.sync.aligned.m16n8k8.row.col.f32.tf32.tf32.f32 "
        "{%0,%1,%2,%3}, {%4,%5,%6,%7}, {%8,%9}, {%0,%1,%2,%3};"
        : "+f"(d[0]), "+f"(d[1]), "+f"(d[2]), "+f"(d[3])
        : "r"(__float_as_uint(a[0])), "r"(__float_as_uint(a[1])),
          "r"(__float_as_uint(a[2])), "r"(__float_as_uint(a[3])),
          "r"(__float_as_uint(b[0])), "r"(__float_as_uint(b[1])));
}

__device__ __forceinline__ void cp_async16(uint32_t dst, const void* src) {
    asm volatile("cp.async.cg.shared.global [%0], [%1], 16;"
                 :: "r"(dst), "l"(src) : "memory");
}

__device__ __forceinline__ float tanh_fast(float x) {
    float r;
    asm("tanh.approx.f32 %0, %1;" : "=f"(r) : "f"(x));
    return r;
}

#define MBAR_INIT(addr, cnt) \
    asm volatile("mbarrier.init.shared.b64 [%0], %1;" \
                 :: "r"((uint32_t)(addr)), "r"((uint32_t)(cnt)) : "memory")

#define MBAR_ARRIVE_RANK(local_addr, rk)                                        \
    asm volatile("{\n\t.reg .b32 ra;\n\t"                                       \
        "mapa.shared::cluster.u32 ra, %0, %1;\n\t"                              \
        "mbarrier.arrive.release.cluster.shared::cluster.b64 _, [ra];\n\t}"     \
        :: "r"((uint32_t)(local_addr)), "r"((uint32_t)(rk)) : "memory")

#define MBAR_WAIT(addr, par) do {                                               \
    uint32_t _m = (uint32_t)(addr); uint32_t _p = (uint32_t)(par); uint32_t _d; \
    asm volatile("{\n\t.reg .pred p;\n\t"                                       \
        "mbarrier.try_wait.parity.acquire.cluster.shared::cta.b64 p, [%1], %2;\n\t" \
        "selp.b32 %0, 1, 0, p;\n\t}"                                            \
        : "=r"(_d) : "r"(_m), "r"(_p) : "memory");                              \
    if (!_d) {                                                                  \
        asm volatile("{\n\t.reg .pred P1;\n\t"                                  \
            "WL_%=:\n\t"                                                        \
            "mbarrier.try_wait.parity.acquire.cluster.shared::cta.b64 P1, [%0], %1, 0x989680;\n\t" \
            "@P1 bra.uni WD_%=;\n\t"                                            \
            "bra.uni WL_%=;\n\t"                                                \
            "WD_%=:\n\t}"                                                       \
            :: "r"(_m), "r"(_p) : "memory");                                    \
    }                                                                           \
} while (0)

// =============================================================================
// Elementwise tf32-RNA pre-rounding (vectorized)
// =============================================================================
__global__ __launch_bounds__(256) void cvt_tf32_kernel(
    const float* __restrict__ s, float* __restrict__ d, int n4)
{
    const int i = blockIdx.x * 256 + threadIdx.x;
    if (i < n4) {
        float4 v = ((const float4*)s)[i];
        v.x = f2tf32(v.x); v.y = f2tf32(v.y);
        v.z = f2tf32(v.z); v.w = f2tf32(v.w);
        ((float4*)d)[i] = v;
    }
}

// =============================================================================
// gi GEMM v4: 64x64 warp tiles (4 warps, 128 threads), BK=16, 4-stage cp.async.
//  C[M,N] = A[M,K] @ Bw[N,K]^T + bias[N]; A/Bw pre-rounded tf32.
//  Per 8-k: 32 MMAs on 16 LDS.64 (ratio 0.5 vs 0.75 in v2); CTA LDS/stage
//  192 -> 128; 2x per-warp MMA ILP. Pitch 24, k-permuted: conflict-free
//  (per 16-lane phase rows gid*12 mod 16 = {0,12,8,4}).
//  Accumulation order per output element identical to v2 -> bit-identical C.
// =============================================================================
#define GP    24
#define GSTG  4
#define GEMM_SMEM_BYTES (GSTG * 2 * 128 * GP * 4)   // 98,304

__global__ __launch_bounds__(128, 2) void gemm_tf32_pipe(
    const float* __restrict__ A, const float* __restrict__ Bw,
    const float* __restrict__ bias, float* __restrict__ C,
    int N, int K)
{
    extern __shared__ float gsm[];
    const uint32_t smb = (uint32_t)__cvta_generic_to_shared(gsm);

    const int t    = threadIdx.x;     // 0..127
    const int bx   = blockIdx.x;
    const int by   = blockIdx.y;
    const int lane = t & 31;
    const int w    = t >> 5;          // 0..3
    const int wm   = w & 1;           // M half
    const int wn   = w >> 1;          // N half
    const int gid  = lane >> 2;
    const int tig  = lane & 3;

    const float* Agm = A  + (size_t)(by * 128) * K;
    const float* Bgm = Bw + (size_t)(bx * 128) * K;

    // copy identity: thread owns row t of BOTH arrays, 4 float4 chunks each
    const uint32_t a_dst0 = smb + (uint32_t)(t * GP) * 4;
    const uint32_t b_dst0 = a_dst0 + (uint32_t)(GSTG * 128 * GP) * 4;
    const float* a_src0 = Agm + (size_t)t * K;
    const float* b_src0 = Bgm + (size_t)t * K;

    const int nst = K >> 4;

#define G_ISSUE(s_) do {                                                      \
    const uint32_t so_ = (uint32_t)(((s_) & (GSTG - 1)) * 128 * GP) * 4;      \
    const int ko_ = (s_) * 16;                                                \
    cp_async16(a_dst0 + so_,      a_src0 + ko_);                              \
    cp_async16(a_dst0 + so_ + 16, a_src0 + ko_ + 4);                          \
    cp_async16(a_dst0 + so_ + 32, a_src0 + ko_ + 8);                          \
    cp_async16(a_dst0 + so_ + 48, a_src0 + ko_ + 12);                         \
    cp_async16(b_dst0 + so_,      b_src0 + ko_);                              \
    cp_async16(b_dst0 + so_ + 16, b_src0 + ko_ + 4);                          \
    cp_async16(b_dst0 + so_ + 32, b_src0 + ko_ + 8);                          \
    cp_async16(b_dst0 + so_ + 48, b_src0 + ko_ + 12);                         \
    asm volatile("cp.async.commit_group;" ::: "memory");                      \
} while (0)

    // prologue: stages 0..2
    G_ISSUE(0);
    G_ISSUE(1);
    G_ISSUE(2);

    float acc[4][8][4];
#pragma unroll
    for (int i = 0; i < 4; i++)
#pragma unroll
        for (int jx = 0; jx < 8; jx++)
#pragma unroll
            for (int q = 0; q < 4; q++) acc[i][jx][q] = 0.0f;

    const int m_base = wm * 64;
    const int n_base = wn * 64;

    for (int s = 0; s < nst; s++) {
        asm volatile("cp.async.wait_group 2;" ::: "memory");
        __syncthreads();                       // stage s visible; buf(s-1) free
        if (s + GSTG - 1 < nst) G_ISSUE(s + GSTG - 1);

        const float* Asb = gsm + (s & (GSTG - 1)) * 128 * GP;
        const float* Bsb = Asb + GSTG * 128 * GP;

#pragma unroll
        for (int kk = 0; kk < 16; kk += 8) {
            const int kc = kk + 2 * tig;
            float a[4][4], b[8][2];
#pragma unroll
            for (int i = 0; i < 4; i++) {
                const int m0 = m_base + i * 16;
                const float2 lo = *(const float2*)(Asb + (m0 + gid) * GP + kc);
                const float2 hi = *(const float2*)(Asb + (m0 + gid + 8) * GP + kc);
                a[i][0] = lo.x; a[i][1] = hi.x; a[i][2] = lo.y; a[i][3] = hi.y;
            }
#pragma unroll
            for (int jx = 0; jx < 8; jx++) {
                const float2 bv = *(const float2*)(Bsb + (n_base + jx * 8 + gid) * GP + kc);
                b[jx][0] = bv.x; b[jx][1] = bv.y;
            }
#pragma unroll
            for (int i = 0; i < 4; i++)
#pragma unroll
                for (int jx = 0; jx < 8; jx++)
                    mma_tf32(acc[i][jx], a[i], b[jx]);
        }
        __syncthreads();                       // all reads of stage s done
    }

    // ---- epilogue: bias + store ----
#pragma unroll
    for (int i = 0; i < 4; i++) {
        const int m0 = by * 128 + m_base + i * 16 + gid;
#pragma unroll
        for (int jx = 0; jx < 8; jx++) {
            const int n = bx * 128 + n_base + jx * 8 + tig * 2;
            const float b0 = __ldg(bias + n);
            const float b1 = __ldg(bias + n + 1);
            float2 v0, v1;
            v0.x = acc[i][jx][0] + b0;  v0.y = acc[i][jx][1] + b1;
            v1.x = acc[i][jx][2] + b0;  v1.y = acc[i][jx][3] + b1;
            *(float2*)(C + (size_t)m0 * N + n)       = v0;
            *(float2*)(C + (size_t)(m0 + 8) * N + n) = v1;
        }
    }
#undef G_ISSUE
}

// =============================================================================
// HMMA persistent GRU recurrence, v7 (round-14 champion, REVERTED exactly:
// 745us measured twice; round-15's v8 re-partition regressed to 835us).
// =============================================================================
#define HPITCH 264
#define OFF_HBUF(par) ((par) * (8 * HPITCH))            // 2 x 2112
#define OFF_GH        (2 * 8 * HPITCH)                  // 4224; 8x200 = 1600
#define OFF_GIS(par)  (OFF_GH + 1600 + (par) * 1536)
#define OFF_BHH       (OFF_GH + 1600 + 2 * 1536)        // 192
#define OFF_MBAR      (OFF_BHH + 192)                   // 8B aligned
#define REC_SMEM_BYTES ((OFF_MBAR + 4) * 4)             // 36,368 B

__global__ void __cluster_dims__(4, 1, 1) __launch_bounds__(384, 1)
gru_rec_mma(const float* __restrict__ Whh, const float* __restrict__ bhh_g,
            const float* __restrict__ gi, float* __restrict__ hout,
            int store_all)
{
    extern __shared__ float smf[];
    float* bhh = smf + OFF_BHH;
    float* gh  = smf + OFF_GH;
    const uint32_t mbar = (uint32_t)__cvta_generic_to_shared(smf + OFF_MBAR);

    cg::cluster_group cluster = cg::this_cluster();
    const int rank = cluster.block_rank();
    const int B0   = (blockIdx.x >> 2) * 8;

    const int t    = threadIdx.x;
    const int lane = t & 31;
    const int w    = t >> 5;
    const int gid  = lane >> 2;
    const int tig  = lane & 3;

    // W_hh fragments -> registers, k permuted (slot tig -> 2tig, tig+4 -> 2tig+1)
    float wa0[32], wa1[32], wa2[32], wa3[32];
    {
        const int g  = w >> 2;
        const int r0 = g * 256 + rank * 64 + (w & 3) * 16 + gid;
        const float* p0 = Whh + (size_t)r0 * 256;
        const float* p1 = p0 + 8 * 256;
#pragma unroll
        for (int s = 0; s < 32; s++) {
            wa0[s] = f2tf32(p0[8 * s + 2 * tig]);
            wa1[s] = f2tf32(p1[8 * s + 2 * tig]);
            wa2[s] = f2tf32(p0[8 * s + 2 * tig + 1]);
            wa3[s] = f2tf32(p1[8 * s + 2 * tig + 1]);
        }
    }
    for (int i = t; i < 192; i += 384)
        bhh[i] = bhh_g[((i >> 6) << 8) + rank * 64 + (i & 63)];
    for (int i = t; i < 2 * 8 * HPITCH; i += 384) smf[i] = 0.0f;
    if (t == 0) MBAR_INIT(mbar, 4);
    __syncthreads();
    cluster.sync();
    if (t < 4) MBAR_ARRIVE_RANK(mbar, t);

    const int j     = t & 63;
    const int bb    = (t >> 6) & 3;
    const int kglob = rank * 64 + j;
    float hprev0 = 0.0f, hprev1 = 0.0f;

    const int cb   = t / 48;
    const int crem = t % 48;
    const int cg_  = crem >> 4;
    const int cq   = crem & 15;
    const uint32_t gis_dst0 = (uint32_t)__cvta_generic_to_shared(
        smf + OFF_GIS(0) + cb * 192 + cg_ * 64 + cq * 4);
    const float* gi_src0 = gi + ((size_t)B0 + cb) * G3 + cg_ * 256 + rank * 64 + cq * 4;

    cp_async16(gis_dst0, gi_src0);
    asm volatile("cp.async.commit_group;" ::: "memory");

    for (int ts = 0; ts < T_STEPS; ts++) {
        const int par = ts & 1;
        {
            const int tn = (ts + 1 < T_STEPS) ? (ts + 1) : ts;
            cp_async16(gis_dst0 + (par ^ 1) * 1536 * 4,
                       gi_src0 + (size_t)tn * BATCH * G3);
            asm volatile("cp.async.commit_group;" ::: "memory");
        }

        MBAR_WAIT(mbar, par);

        {
            float c0[4] = {0, 0, 0, 0}, c1[4] = {0, 0, 0, 0};
            float c2[4] = {0, 0, 0, 0}, c3[4] = {0, 0, 0, 0};
            const float* hb = smf + OFF_HBUF(par) + gid * HPITCH + 2 * tig;
#pragma unroll
            for (int s = 0; s < 32; s += 4) {
                const float2 h0 = *(const float2*)(hb + ((s + 0) << 3));
                const float2 h1 = *(const float2*)(hb + ((s + 1) << 3));
                const float2 h2 = *(const float2*)(hb + ((s + 2) << 3));
                const float2 h3 = *(const float2*)(hb + ((s + 3) << 3));
                float b0[2] = { h0.x, h0.y };
                float b1[2] = { h1.x, h1.y };
                float b2[2] = { h2.x, h2.y };
                float b3[2] = { h3.x, h3.y };
                float w0[4] = { wa0[s + 0], wa1[s + 0], wa2[s + 0], wa3[s + 0] };
                float w1[4] = { wa0[s + 1], wa1[s + 1], wa2[s + 1], wa3[s + 1] };
                float w2[4] = { wa0[s + 2], wa1[s + 2], wa2[s + 2], wa3[s + 2] };
                float w3[4] = { wa0[s + 3], wa1[s + 3], wa2[s + 3], wa3[s + 3] };
                mma_tf32(c0, w0, b0);
                mma_tf32(c1, w1, b1);
                mma_tf32(c2, w2, b2);
                mma_tf32(c3, w3, b3);
            }
            const int lr = w * 16 + gid;
            const int bi = tig * 2;
            gh[(bi    ) * 200 + lr    ] = (c0[0] + c1[0]) + (c2[0] + c3[0]);
            gh[(bi + 1) * 200 + lr    ] = (c0[1] + c1[1]) + (c2[1] + c3[1]);
            gh[(bi    ) * 200 + lr + 8] = (c0[2] + c1[2]) + (c2[2] + c3[2]);
            gh[(bi + 1) * 200 + lr + 8] = (c0[3] + c1[3]) + (c2[3] + c3[3]);
        }
        asm volatile("cp.async.wait_group 1;" ::: "memory");
        __syncthreads();

        if (t < 256) {
            const float* gis = smf + OFF_GIS(par);
            float* hwr = smf + OFF_HBUF(par ^ 1);
            const float br = bhh[j], bz = bhh[64 + j], bn = bhh[128 + j];
#pragma unroll
            for (int i = 0; i < 2; i++) {
                const int b = bb + 4 * i;
                const float hr = gh[b * 200 + j]       + br;
                const float hz = gh[b * 200 + 64 + j]  + bz;
                const float hn = gh[b * 200 + 128 + j] + bn;
                const float ir  = gis[b * 192 + j];
                const float iz  = gis[b * 192 + 64 + j];
                const float in_ = gis[b * 192 + 128 + j];
                const float r = __fdividef(1.0f, 1.0f + __expf(-(ir + hr)));
                const float z = __fdividef(1.0f, 1.0f + __expf(-(iz + hz)));
                const float n = tanh_fast(in_ + r * hn);
                const float hprev = (i == 0) ? hprev0 : hprev1;
                const float hnew  = (1.0f - z) * n + z * hprev;
                if (i == 0) hprev0 = hnew; else hprev1 = hnew;

                const float hop = f2tf32(hnew);
                float* lp = hwr + b * HPITCH + kglob;
#pragma unroll
                for (int q = 0; q < 4; q++)
                    *(float*)cluster.map_shared_rank(lp, q) = hop;

                if (store_all) {
                    hout[((size_t)ts * BATCH + B0 + b) * HID + kglob] = hop;
                } else if (ts == T_STEPS - 1) {
                    hout[(size_t)(B0 + b) * HID + kglob] = hnew;
                }
            }
        }
        __syncthreads();
        if (t < 4) MBAR_ARRIVE_RANK(mbar, t);
    }

    cluster.sync();
}

// =============================================================================
// FC on the last hidden state
// =============================================================================
__global__ __launch_bounds__(256) void fc_kernel(
    const float* __restrict__ Wfc, const float* __restrict__ bfc,
    float* __restrict__ out)
{
    __shared__ float hs[256];
    const int b = blockIdx.x;
    const int o = threadIdx.x;
    hs[o] = g_h2[b * 256 + o];
    __syncthreads();
    const float* wr = Wfc + (size_t)o * 256;
    float acc = 0.0f;
#pragma unroll 8
    for (int k = 0; k < 256; k += 4) {
        const float4 wv = *(const float4*)(wr + k);
        acc += hs[k] * wv.x + hs[k + 1] * wv.y + hs[k + 2] * wv.z + hs[k + 3] * wv.w;
    }
    out[b * 256 + o] = acc + bfc[o];
}

// =============================================================================
extern "C" void kernel_launch(void* const* d_in, const int* in_sizes, int n_in,
                              void* d_out, int out_size)
{
    const float* x     = (const float*)d_in[0];
    const float* W_ih0 = (const float*)d_in[1];
    const float* W_hh0 = (const float*)d_in[2];
    const float* b_ih0 = (const float*)d_in[3];
    const float* b_hh0 = (const float*)d_in[4];
    const float* W_ih1 = (const float*)d_in[5];
    const float* W_hh1 = (const float*)d_in[6];
    const float* b_ih1 = (const float*)d_in[7];
    const float* b_hh1 = (const float*)d_in[8];
    const float* W_fc  = (const float*)d_in[9];
    const float* b_fc  = (const float*)d_in[10];
    float* out = (float*)d_out;

    float *gi_p, *h1_p, *h2_p, *xt_p, *wt_p;
    cudaGetSymbolAddress((void**)&gi_p, g_gi);
    cudaGetSymbolAddress((void**)&h1_p, g_h1);
    cudaGetSymbolAddress((void**)&h2_p, g_h2);
    cudaGetSymbolAddress((void**)&xt_p, g_xt);
    cudaGetSymbolAddress((void**)&wt_p, g_wt);

    cudaFuncSetAttribute(gru_rec_mma, cudaFuncAttributeMaxDynamicSharedMemorySize,
                         REC_SMEM_BYTES);
    cudaFuncSetAttribute(gemm_tf32_pipe, cudaFuncAttributeMaxDynamicSharedMemorySize,
                         GEMM_SMEM_BYTES);

    const int M = T_STEPS * BATCH;        // 131072
    dim3 gemm_grid(G3 / 128, M / 128);    // (6, 1024)

    // pre-round x and W_ih0 to tf32 (RNA)
    {
        const int n4x = (M * IN0) / 4;
        cvt_tf32_kernel<<<(n4x + 255) / 256, 256>>>(x, xt_p, n4x);
        const int n4w = (G3 * IN0) / 4;
        cvt_tf32_kernel<<<(n4w + 255) / 256, 256>>>(W_ih0, wt_p, n4w);
    }
    // layer 0: gi0 = x @ W_ih0^T + b_ih0   (64x64 warp-tile tf32 HMMA)
    gemm_tf32_pipe<<<gemm_grid, 128, GEMM_SMEM_BYTES>>>(xt_p, wt_p, b_ih0, gi_p, G3, IN0);
    // layer 0 recurrence -> g_h1[T,B,H] (stored pre-rounded tf32)
    gru_rec_mma<<<128, 384, REC_SMEM_BYTES>>>(W_hh0, b_hh0, gi_p, h1_p, 1);
    // pre-round W_ih1
    {
        const int n4w = (G3 * HID) / 4;
        cvt_tf32_kernel<<<(n4w + 255) / 256, 256>>>(W_ih1, wt_p, n4w);
    }
    // layer 1: gi1 = h1 @ W_ih1^T + b_ih1  (64x64 warp-tile tf32 HMMA)
    gemm_tf32_pipe<<<gemm_grid, 128, GEMM_SMEM_BYTES>>>(h1_p, wt_p, b_ih1, gi_p, G3, HID);
    // layer 1 recurrence -> g_h2[B,H]
    gru_rec_mma<<<128, 384, REC_SMEM_BYTES>>>(W_hh1, b_hh1, gi_p, h2_p, 0);
    // FC head
    fc_kernel<<<BATCH, 256>>>(W_fc, b_fc, out);
}